// round 1
// baseline (speedup 1.0000x reference)
#include <cuda_runtime.h>
#include <cstdint>
#include <math.h>

#define S_LEN 2048
#define B_SZ  8
#define D_DIM 1024
#define E_NUM 8
#define H_DIM 512
#define M_TOK (S_LEN * B_SZ)          // 16384 tokens
#define N1    (E_NUM * H_DIM)         // 4096

#define AS_STRIDE 36                  // 32 + 4 pad -> conflict-free A frag reads
#define BS_STRIDE 136                 // 128 + 8 pad -> conflict-free B frag reads
#define GEMM_SMEM_BYTES ((2*128*AS_STRIDE + 2*32*BS_STRIDE) * 4)

// ---- scratch (allocation-free rule: __device__ globals) ----
__device__ float g_h[(size_t)M_TOK * N1];     // 268 MB fc1 activations
__device__ float g_mu[M_TOK];
__device__ float g_rstd[M_TOK];
__device__ float g_sx[B_SZ * D_DIM];          // sentence max-pool
__device__ float g_gates[B_SZ * E_NUM];
__device__ float g_b2g[B_SZ * D_DIM];         // sum_e gates[b,e]*b2[e,:]

// ===================== small kernels =====================

// per-token LayerNorm stats (biased var, eps 1e-5)
__global__ void k_stats(const float* __restrict__ x) {
    const int m = blockIdx.x;
    const float4* row = (const float4*)(x + (size_t)m * D_DIM);
    const int t = threadIdx.x;  // 128 threads
    float4 v0 = row[t];
    float4 v1 = row[t + 128];
    float s = v0.x + v0.y + v0.z + v0.w + v1.x + v1.y + v1.z + v1.w;
    float q = v0.x*v0.x + v0.y*v0.y + v0.z*v0.z + v0.w*v0.w
            + v1.x*v1.x + v1.y*v1.y + v1.z*v1.z + v1.w*v1.w;
    #pragma unroll
    for (int o = 16; o; o >>= 1) {
        s += __shfl_xor_sync(0xFFFFFFFFu, s, o);
        q += __shfl_xor_sync(0xFFFFFFFFu, q, o);
    }
    __shared__ float ss[4], sq[4];
    if ((t & 31) == 0) { ss[t >> 5] = s; sq[t >> 5] = q; }
    __syncthreads();
    if (t == 0) {
        float S2 = ss[0] + ss[1] + ss[2] + ss[3];
        float Q  = sq[0] + sq[1] + sq[2] + sq[3];
        float mu = S2 * (1.0f / D_DIM);
        float var = Q * (1.0f / D_DIM) - mu * mu;
        g_mu[m] = mu;
        g_rstd[m] = rsqrtf(var + 1e-5f);
    }
}

// masked max over sequence -> sentence_x[b, d]
__global__ void k_maxpool(const float* __restrict__ x,
                          const unsigned char* __restrict__ pad) {
    const int b  = blockIdx.x >> 3;
    const int d0 = (blockIdx.x & 7) * 128;
    const int t  = threadIdx.x;  // 128
    __shared__ float neg[S_LEN];
    for (int s = t; s < S_LEN; s += 128)
        neg[s] = pad[b * S_LEN + s] ? -1e30f : 0.0f;
    __syncthreads();
    const int d = d0 + t;
    const float* base = x + (size_t)b * D_DIM + d;
    float m0 = -INFINITY, m1 = -INFINITY, m2 = -INFINITY, m3 = -INFINITY;
    #pragma unroll 1
    for (int s = 0; s < S_LEN; s += 4) {
        m0 = fmaxf(m0, base[(size_t)(s + 0) * (B_SZ * D_DIM)] + neg[s + 0]);
        m1 = fmaxf(m1, base[(size_t)(s + 1) * (B_SZ * D_DIM)] + neg[s + 1]);
        m2 = fmaxf(m2, base[(size_t)(s + 2) * (B_SZ * D_DIM)] + neg[s + 2]);
        m3 = fmaxf(m3, base[(size_t)(s + 3) * (B_SZ * D_DIM)] + neg[s + 3]);
    }
    g_sx[b * D_DIM + d] = fmaxf(fmaxf(m0, m1), fmaxf(m2, m3));
}

// gating: logits, softmax + renorm, gate-weighted b2
__global__ void k_gate(const float* __restrict__ gw,
                       const float* __restrict__ b2,
                       float* __restrict__ out_logits) {
    const int t = threadIdx.x;  // 256
    __shared__ float logits[B_SZ * E_NUM];
    __shared__ float gsh[B_SZ * E_NUM];
    if (t < B_SZ * E_NUM) {
        const int b = t >> 3, e = t & 7;
        const float4* sx = (const float4*)(g_sx + b * D_DIM);
        const float4* w  = (const float4*)(gw + e * D_DIM);
        float acc = 0.0f;
        for (int k = 0; k < D_DIM / 4; k++) {
            float4 a = sx[k]; float4 ww = w[k];
            acc += a.x * ww.x + a.y * ww.y + a.z * ww.z + a.w * ww.w;
        }
        logits[t] = acc;
        out_logits[b * E_NUM + e] = acc;
    }
    __syncthreads();
    if (t < B_SZ) {
        const float TEMP = 1.0f;
        float mx = -INFINITY;
        for (int e = 0; e < E_NUM; e++) mx = fmaxf(mx, logits[t * E_NUM + e] / TEMP);
        float p[E_NUM]; float ssum = 0.0f;
        for (int e = 0; e < E_NUM; e++) { p[e] = expf(logits[t * E_NUM + e] / TEMP - mx); ssum += p[e]; }
        float s2 = 0.0f;
        for (int e = 0; e < E_NUM; e++) { p[e] /= ssum; s2 += p[e]; }
        for (int e = 0; e < E_NUM; e++) {
            float gv = p[e] / (s2 + 1e-9f);
            gsh[t * E_NUM + e] = gv;
            g_gates[t * E_NUM + e] = gv;
        }
    }
    __syncthreads();
    for (int i = t; i < B_SZ * D_DIM; i += 256) {
        const int b = i >> 10, d = i & 1023;
        float acc = 0.0f;
        #pragma unroll
        for (int e = 0; e < E_NUM; e++) acc += gsh[b * E_NUM + e] * b2[e * D_DIM + d];
        g_b2g[i] = acc;
    }
}

// ===================== TF32 tensor-core GEMM =====================

__device__ __forceinline__ float to_tf32(float x) {
    uint32_t u;
    asm("cvt.rna.tf32.f32 %0, %1;" : "=r"(u) : "f"(x));
    return __uint_as_float(u);
}

__device__ __forceinline__ void mma_tf32(float c[4], const uint32_t a[4], const uint32_t b[2]) {
    asm volatile(
        "mma.sync.aligned.m16n8k8.row.col.f32.tf32.tf32.f32 "
        "{%0,%1,%2,%3}, {%4,%5,%6,%7}, {%8,%9}, {%0,%1,%2,%3};"
        : "+f"(c[0]), "+f"(c[1]), "+f"(c[2]), "+f"(c[3])
        : "r"(a[0]), "r"(a[1]), "r"(a[2]), "r"(a[3]), "r"(b[0]), "r"(b[1]));
}

// MODE 0: fc1  h = relu(LN(x) @ W1cat + b1) * gate   (A = x with fused LN, B = w1, out -> g_h)
// MODE 1: fc2  out = g_h @ W2cat + x + b2g           (A = g_h, B = w2, out -> d_out)
template<int MODE>
__device__ __forceinline__ void load_tile(
    const float* __restrict__ A, const float* __restrict__ Bbase, int Bstride,
    const float* __restrict__ gamma, const float* __restrict__ beta,
    int m0, int k0, int ar, int ac, int br, int bc,
    float4 aR[4], float4 bR[4])
{
    float4 ga, be;
    if (MODE == 0) {
        ga = *(const float4*)(gamma + k0 + ac);
        be = *(const float4*)(beta + k0 + ac);
    }
    const int astr = (MODE == 0) ? D_DIM : N1;
    #pragma unroll
    for (int p = 0; p < 4; p++) {
        const int m = m0 + ar + p * 32;
        float4 v = *(const float4*)(A + (size_t)m * astr + k0 + ac);
        if (MODE == 0) {
            const float mu = g_mu[m], rs = g_rstd[m];
            v.x = (v.x - mu) * rs * ga.x + be.x;
            v.y = (v.y - mu) * rs * ga.y + be.y;
            v.z = (v.z - mu) * rs * ga.z + be.z;
            v.w = (v.w - mu) * rs * ga.w + be.w;
        }
        v.x = to_tf32(v.x); v.y = to_tf32(v.y); v.z = to_tf32(v.z); v.w = to_tf32(v.w);
        aR[p] = v;
    }
    #pragma unroll
    for (int p = 0; p < 4; p++) {
        const int kr = k0 + br + p * 8;
        float4 v = *(const float4*)(Bbase + (size_t)kr * Bstride + bc);
        v.x = to_tf32(v.x); v.y = to_tf32(v.y); v.z = to_tf32(v.z); v.w = to_tf32(v.w);
        bR[p] = v;
    }
}

__device__ __forceinline__ void store_tile(float* As, float* Bs,
    int ar, int ac, int br, int bc, const float4 aR[4], const float4 bR[4])
{
    #pragma unroll
    for (int p = 0; p < 4; p++)
        *(float4*)(As + (ar + p * 32) * AS_STRIDE + ac) = aR[p];
    #pragma unroll
    for (int p = 0; p < 4; p++)
        *(float4*)(Bs + (br + p * 8) * BS_STRIDE + bc) = bR[p];
}

template<int MODE>
__global__ void __launch_bounds__(256, 1)
k_gemm(const float* __restrict__ Ain, const float* __restrict__ Bmat,
       const float* __restrict__ gamma, const float* __restrict__ beta,
       const float* __restrict__ bias1, const float* __restrict__ xres,
       float* __restrict__ Cout, int K)
{
    const int m0 = blockIdx.y * 128;
    const int n0 = blockIdx.x * 128;
    const int tid = threadIdx.x;

    extern __shared__ float smem[];
    float* As = smem;                              // [2][128][AS_STRIDE]
    float* Bs = smem + 2 * 128 * AS_STRIDE;        // [2][32][BS_STRIDE]

    const float* A = (MODE == 0) ? Ain : g_h;

    const float* Bbase;
    int Bstride;
    if (MODE == 0) {
        const int e = n0 >> 9;                     // expert for this N-tile
        Bbase = Bmat + (size_t)e * D_DIM * H_DIM + (n0 & 511);
        Bstride = H_DIM;
    } else {
        Bbase = Bmat + n0;
        Bstride = D_DIM;
    }

    // global loader indices
    const int ar = tid >> 3;            // 0..31 (row within pass)
    const int ac = (tid & 7) * 4;       // 0..28
    const int br = tid >> 5;            // 0..7
    const int bc = (tid & 31) * 4;      // 0..124

    // warp / lane indices
    const int wid = tid >> 5;
    const int lane = tid & 31;
    const int wm = (wid >> 2) * 64;     // 0 or 64
    const int wn = (wid & 3) * 32;      // 0,32,64,96
    const int g  = lane >> 2;           // 0..7
    const int tq = lane & 3;            // 0..3

    float c[4][4][4];
    #pragma unroll
    for (int i = 0; i < 4; i++)
        #pragma unroll
        for (int j = 0; j < 4; j++)
            #pragma unroll
            for (int r = 0; r < 4; r++) c[i][j][r] = 0.0f;

    const int KT = K / 32;
    float4 aR[4], bR[4];

    load_tile<MODE>(A, Bbase, Bstride, gamma, beta, m0, 0, ar, ac, br, bc, aR, bR);
    store_tile(As, Bs, ar, ac, br, bc, aR, bR);
    __syncthreads();

    for (int kt = 0; kt < KT; kt++) {
        const int buf = kt & 1;
        if (kt + 1 < KT)
            load_tile<MODE>(A, Bbase, Bstride, gamma, beta, m0, (kt + 1) * 32,
                            ar, ac, br, bc, aR, bR);

        const float* Ab = As + buf * 128 * AS_STRIDE;
        const float* Bb = Bs + buf * 32 * BS_STRIDE;

        #pragma unroll
        for (int s = 0; s < 4; s++) {
            uint32_t af[4][4], bf[4][2];
            #pragma unroll
            for (int i = 0; i < 4; i++) {
                const int row = wm + i * 16 + g;
                const int col = 8 * s + tq;
                af[i][0] = __float_as_uint(Ab[row * AS_STRIDE + col]);
                af[i][1] = __float_as_uint(Ab[(row + 8) * AS_STRIDE + col]);
                af[i][2] = __float_as_uint(Ab[row * AS_STRIDE + col + 4]);
                af[i][3] = __float_as_uint(Ab[(row + 8) * AS_STRIDE + col + 4]);
            }
            #pragma unroll
            for (int j = 0; j < 4; j++) {
                const int coln = wn + j * 8 + g;
                bf[j][0] = __float_as_uint(Bb[(8 * s + tq) * BS_STRIDE + coln]);
                bf[j][1] = __float_as_uint(Bb[(8 * s + tq + 4) * BS_STRIDE + coln]);
            }
            #pragma unroll
            for (int i = 0; i < 4; i++)
                #pragma unroll
                for (int j = 0; j < 4; j++)
                    mma_tf32(c[i][j], af[i], bf[j]);
        }

        if (kt + 1 < KT)
            store_tile(As + (buf ^ 1) * 128 * AS_STRIDE,
                       Bs + (buf ^ 1) * 32 * BS_STRIDE, ar, ac, br, bc, aR, bR);
        __syncthreads();
    }

    // ---- epilogues ----  (m % 8 == g for every owned row: block/warp/tile offsets are multiples of 8)
    if (MODE == 0) {
        const int e = n0 >> 9;
        const float gate = g_gates[g * E_NUM + e];
        #pragma unroll
        for (int i = 0; i < 4; i++) {
            const int m1 = m0 + wm + i * 16 + g;
            #pragma unroll
            for (int j = 0; j < 4; j++) {
                const int nc = n0 + wn + j * 8 + 2 * tq;
                const float b0v = bias1[nc], b1v = bias1[nc + 1];
                float2 v;
                v.x = fmaxf(c[i][j][0] + b0v, 0.0f) * gate;
                v.y = fmaxf(c[i][j][1] + b1v, 0.0f) * gate;
                *(float2*)(g_h + (size_t)m1 * N1 + nc) = v;
                v.x = fmaxf(c[i][j][2] + b0v, 0.0f) * gate;
                v.y = fmaxf(c[i][j][3] + b1v, 0.0f) * gate;
                *(float2*)(g_h + (size_t)(m1 + 8) * N1 + nc) = v;
            }
        }
    } else {
        #pragma unroll
        for (int i = 0; i < 4; i++) {
            const int m1 = m0 + wm + i * 16 + g;
            #pragma unroll
            for (int j = 0; j < 4; j++) {
                const int nc = n0 + wn + j * 8 + 2 * tq;
                const float2 bg = *(const float2*)(g_b2g + g * D_DIM + nc);
                float2 r0 = *(const float2*)(xres + (size_t)m1 * D_DIM + nc);
                float2 v;
                v.x = c[i][j][0] + r0.x + bg.x;
                v.y = c[i][j][1] + r0.y + bg.y;
                *(float2*)(Cout + (size_t)m1 * D_DIM + nc) = v;
                float2 r1 = *(const float2*)(xres + (size_t)(m1 + 8) * D_DIM + nc);
                v.x = c[i][j][2] + r1.x + bg.x;
                v.y = c[i][j][3] + r1.y + bg.y;
                *(float2*)(Cout + (size_t)(m1 + 8) * D_DIM + nc) = v;
            }
        }
    }
}

// ===================== launch =====================

extern "C" void kernel_launch(void* const* d_in, const int* in_sizes, int n_in,
                              void* d_out, int out_size) {
    if (n_in < 9) return;
    const float*         x   = (const float*)d_in[0];
    const unsigned char* pad = (const unsigned char*)d_in[1];
    const float*         gw  = (const float*)d_in[2];
    const float*         gam = (const float*)d_in[3];
    const float*         bet = (const float*)d_in[4];
    const float*         w1  = (const float*)d_in[5];
    const float*         b1  = (const float*)d_in[6];
    const float*         w2  = (const float*)d_in[7];
    const float*         b2  = (const float*)d_in[8];
    float* out = (float*)d_out;
    float* out_logits = out + (size_t)M_TOK * D_DIM;

    cudaFuncSetAttribute(k_gemm<0>, cudaFuncAttributeMaxDynamicSharedMemorySize, GEMM_SMEM_BYTES);
    cudaFuncSetAttribute(k_gemm<1>, cudaFuncAttributeMaxDynamicSharedMemorySize, GEMM_SMEM_BYTES);

    k_stats<<<M_TOK, 128>>>(x);
    k_maxpool<<<B_SZ * (D_DIM / 128), 128>>>(x, pad);
    k_gate<<<1, 256>>>(gw, b2, out_logits);
    k_gemm<0><<<dim3(N1 / 128, M_TOK / 128), 256, GEMM_SMEM_BYTES>>>(
        x, w1, gam, bet, b1, nullptr, nullptr, D_DIM);
    k_gemm<1><<<dim3(D_DIM / 128, M_TOK / 128), 256, GEMM_SMEM_BYTES>>>(
        nullptr, w2, nullptr, nullptr, nullptr, x, out, N1);
}

// round 5
// speedup vs baseline: 2.2256x; 2.2256x over previous
#include <cuda_runtime.h>
#include <cuda_fp16.h>
#include <cstdint>
#include <math.h>

#define S_LEN 2048
#define B_SZ  8
#define D_DIM 1024
#define E_NUM 8
#define H_DIM 512
#define M_TOK (S_LEN * B_SZ)          // 16384
#define N1    (E_NUM * H_DIM)         // 4096

// ===================== scratch (__device__ globals: no allocs allowed) =====================
__device__ __half g_h  [(size_t)M_TOK * N1];     // fc1 activations (fp16)
__device__ __half g_xn [(size_t)M_TOK * D_DIM];  // LN(x) fp16
__device__ __half g_w1t[(size_t)N1 * D_DIM];     // W1^T per expert: [e*H+h][d]
__device__ __half g_w2t[(size_t)D_DIM * N1];     // W2^T: [d][e*H+h]
__device__ float  g_sx [B_SZ * D_DIM];
__device__ float  g_gates[B_SZ * E_NUM];
__device__ float  g_b2g[B_SZ * D_DIM];

// ===================== helpers =====================
__device__ __forceinline__ uint32_t smem_u32(const void* p) {
    uint32_t a;
    asm("{ .reg .u64 t; cvta.to.shared.u64 t, %1; cvt.u32.u64 %0, t; }" : "=r"(a) : "l"(p));
    return a;
}

#define CP_ASYNC16(dst, src) \
    asm volatile("cp.async.cg.shared.global [%0], [%1], 16;" :: "r"(dst), "l"(src))
#define CP_COMMIT() asm volatile("cp.async.commit_group;" ::: "memory")

__device__ __forceinline__ void ldm_x4(uint32_t r[4], uint32_t addr) {
    asm volatile("ldmatrix.sync.aligned.m8n8.x4.shared.b16 {%0,%1,%2,%3}, [%4];"
        : "=r"(r[0]), "=r"(r[1]), "=r"(r[2]), "=r"(r[3]) : "r"(addr));
}
__device__ __forceinline__ void ldm_x2(uint32_t r[2], uint32_t addr) {
    asm volatile("ldmatrix.sync.aligned.m8n8.x2.shared.b16 {%0,%1}, [%2];"
        : "=r"(r[0]), "=r"(r[1]) : "r"(addr));
}
__device__ __forceinline__ void mma_f16(float c[4], const uint32_t a[4], const uint32_t b[2]) {
    asm volatile(
        "mma.sync.aligned.m16n8k16.row.col.f32.f16.f16.f32 "
        "{%0,%1,%2,%3}, {%4,%5,%6,%7}, {%8,%9}, {%0,%1,%2,%3};"
        : "+f"(c[0]), "+f"(c[1]), "+f"(c[2]), "+f"(c[3])
        : "r"(a[0]), "r"(a[1]), "r"(a[2]), "r"(a[3]), "r"(b[0]), "r"(b[1]));
}

// ===================== prep kernels =====================

// fused LayerNorm -> g_xn (fp16)
__global__ void k_xn(const float* __restrict__ x,
                     const float* __restrict__ gamma, const float* __restrict__ beta) {
    const int m = blockIdx.x, t = threadIdx.x;  // 128 threads
    const float4* row = (const float4*)(x + (size_t)m * D_DIM);
    float4 v0 = row[t], v1 = row[t + 128];
    float s = v0.x + v0.y + v0.z + v0.w + v1.x + v1.y + v1.z + v1.w;
    float q = v0.x*v0.x + v0.y*v0.y + v0.z*v0.z + v0.w*v0.w
            + v1.x*v1.x + v1.y*v1.y + v1.z*v1.z + v1.w*v1.w;
    #pragma unroll
    for (int o = 16; o; o >>= 1) {
        s += __shfl_xor_sync(0xFFFFFFFFu, s, o);
        q += __shfl_xor_sync(0xFFFFFFFFu, q, o);
    }
    __shared__ float ss[4], sq[4], smu, srs;
    if ((t & 31) == 0) { ss[t >> 5] = s; sq[t >> 5] = q; }
    __syncthreads();
    if (t == 0) {
        float S2 = ss[0] + ss[1] + ss[2] + ss[3];
        float Q  = sq[0] + sq[1] + sq[2] + sq[3];
        float mu = S2 * (1.0f / D_DIM);
        smu = mu;
        srs = rsqrtf(Q * (1.0f / D_DIM) - mu * mu + 1e-5f);
    }
    __syncthreads();
    const float mu = smu, rs = srs;
    const float4* gam = (const float4*)gamma;
    const float4* bet = (const float4*)beta;
    __half2* out = (__half2*)(g_xn + (size_t)m * D_DIM);
    #pragma unroll
    for (int h = 0; h < 2; h++) {
        float4 v = (h == 0) ? v0 : v1;
        float4 ga = gam[t + h * 128], be = bet[t + h * 128];
        out[(t + h * 128) * 2 + 0] =
            __floats2half2_rn((v.x - mu) * rs * ga.x + be.x, (v.y - mu) * rs * ga.y + be.y);
        out[(t + h * 128) * 2 + 1] =
            __floats2half2_rn((v.z - mu) * rs * ga.z + be.z, (v.w - mu) * rs * ga.w + be.w);
    }
}

// masked max over sequence -> g_sx[b, d]
__global__ void k_maxpool(const float* __restrict__ x,
                          const unsigned char* __restrict__ pad) {
    const int b  = blockIdx.x >> 3;
    const int d0 = (blockIdx.x & 7) * 128;
    const int t  = threadIdx.x;  // 128
    __shared__ float neg[S_LEN];
    for (int s = t; s < S_LEN; s += 128)
        neg[s] = pad[b * S_LEN + s] ? -1e30f : 0.0f;
    __syncthreads();
    const int d = d0 + t;
    const float* base = x + (size_t)b * D_DIM + d;
    float m0 = -INFINITY, m1 = -INFINITY, m2 = -INFINITY, m3 = -INFINITY;
    #pragma unroll 1
    for (int s = 0; s < S_LEN; s += 4) {
        m0 = fmaxf(m0, base[(size_t)(s + 0) * (B_SZ * D_DIM)] + neg[s + 0]);
        m1 = fmaxf(m1, base[(size_t)(s + 1) * (B_SZ * D_DIM)] + neg[s + 1]);
        m2 = fmaxf(m2, base[(size_t)(s + 2) * (B_SZ * D_DIM)] + neg[s + 2]);
        m3 = fmaxf(m3, base[(size_t)(s + 3) * (B_SZ * D_DIM)] + neg[s + 3]);
    }
    g_sx[b * D_DIM + d] = fmaxf(fmaxf(m0, m1), fmaxf(m2, m3));
}

// gating: logits, softmax + renorm, gate-weighted b2
__global__ void k_gate(const float* __restrict__ gw,
                       const float* __restrict__ b2,
                       float* __restrict__ out_logits) {
    const int t = threadIdx.x;  // 256
    __shared__ float logits[B_SZ * E_NUM];
    __shared__ float gsh[B_SZ * E_NUM];
    if (t < B_SZ * E_NUM) {
        const int b = t >> 3, e = t & 7;
        const float4* sx = (const float4*)(g_sx + b * D_DIM);
        const float4* w  = (const float4*)(gw + e * D_DIM);
        float acc = 0.0f;
        for (int k = 0; k < D_DIM / 4; k++) {
            float4 a = sx[k]; float4 ww = w[k];
            acc += a.x * ww.x + a.y * ww.y + a.z * ww.z + a.w * ww.w;
        }
        logits[t] = acc;
        out_logits[b * E_NUM + e] = acc;
    }
    __syncthreads();
    if (t < B_SZ) {
        float mx = -INFINITY;
        for (int e = 0; e < E_NUM; e++) mx = fmaxf(mx, logits[t * E_NUM + e]);
        float p[E_NUM]; float ssum = 0.0f;
        for (int e = 0; e < E_NUM; e++) { p[e] = expf(logits[t * E_NUM + e] - mx); ssum += p[e]; }
        float s2 = 0.0f;
        for (int e = 0; e < E_NUM; e++) { p[e] /= ssum; s2 += p[e]; }
        for (int e = 0; e < E_NUM; e++) {
            float gv = p[e] / (s2 + 1e-9f);
            gsh[t * E_NUM + e] = gv;
            g_gates[t * E_NUM + e] = gv;
        }
    }
    __syncthreads();
    for (int i = t; i < B_SZ * D_DIM; i += 256) {
        const int b = i >> 10, d = i & 1023;
        float acc = 0.0f;
        #pragma unroll
        for (int e = 0; e < E_NUM; e++) acc += gsh[b * E_NUM + e] * b2[e * D_DIM + d];
        g_b2g[i] = acc;
    }
}

// W1 [E][D][H] -> g_w1t [(e*H+h)][d]  (fp16)
__global__ void k_w1t(const float* __restrict__ w1) {
    __shared__ float tbuf[32][33];
    const int h0 = blockIdx.x * 32, d0 = blockIdx.y * 32, e = blockIdx.z;
    const int tx = threadIdx.x, ty = threadIdx.y;  // (32, 8)
    const float* src = w1 + (size_t)e * D_DIM * H_DIM;
    #pragma unroll
    for (int i = 0; i < 32; i += 8)
        tbuf[ty + i][tx] = src[(size_t)(d0 + ty + i) * H_DIM + h0 + tx];
    __syncthreads();
    __half* dst = g_w1t + (size_t)(e * H_DIM + h0) * D_DIM + d0;
    #pragma unroll
    for (int i = 0; i < 32; i += 8)
        dst[(size_t)(ty + i) * D_DIM + tx] = __float2half_rn(tbuf[tx][ty + i]);
}

// W2 [E*H][D] -> g_w2t [d][E*H]  (fp16)
__global__ void k_w2t(const float* __restrict__ w2) {
    __shared__ float tbuf[32][33];
    const int k0 = blockIdx.x * 32, d0 = blockIdx.y * 32;
    const int tx = threadIdx.x, ty = threadIdx.y;
    #pragma unroll
    for (int i = 0; i < 32; i += 8)
        tbuf[ty + i][tx] = w2[(size_t)(k0 + ty + i) * D_DIM + d0 + tx];
    __syncthreads();
    __half* dst = g_w2t + (size_t)d0 * N1 + k0;
    #pragma unroll
    for (int i = 0; i < 32; i += 8)
        dst[(size_t)(ty + i) * N1 + tx] = __float2half_rn(tbuf[tx][ty + i]);
}

// ===================== fp16 mma.sync GEMM, ldmatrix + cp.async 3-stage =====================
// MODE 0: fc1  g_h = fp16(relu(g_xn @ g_w1t^T + b1) * gate)   [M=16384, N=4096, K=1024]
// MODE 1: fc2  out = g_h @ g_w2t^T + x + b2g                  [M=16384, N=1024, K=4096]

#define TM 128
#define TN 256
#define TK 32
#define NSTAGE 3
#define A_STRIDE_H 40                                  // halfs: 32 + 8 pad = 80 B rows
#define A_STAGE_BYTES (TM * A_STRIDE_H * 2)            // 10240
#define B_STAGE_BYTES (TN * A_STRIDE_H * 2)            // 20480
#define STAGE_BYTES (A_STAGE_BYTES + B_STAGE_BYTES)    // 30720
#define GEMM_SMEM (NSTAGE * STAGE_BYTES + 256)

template<int MODE, int KDIM>
__global__ void __launch_bounds__(256, 1)
k_mm(const float* __restrict__ bias1, const float* __restrict__ xres,
     float* __restrict__ Cout)
{
    extern __shared__ __align__(128) char dsm[];
    const uint32_t smem_base = (smem_u32(dsm) + 127u) & ~127u;

    const int tid = threadIdx.x;
    const int wid = tid >> 5, lane = tid & 31;
    const int m0 = blockIdx.y * TM, n0 = blockIdx.x * TN;
    const int wm = (wid >> 2) * 64;      // 0 or 64
    const int wn = (wid & 3) * 64;       // 0,64,128,192
    const int g  = lane >> 2;            // 0..7
    const int tq = lane & 3;             // 0..3

    const __half* Ag = (MODE == 0) ? g_xn : g_h;
    const __half* Bg = (MODE == 0) ? g_w1t : g_w2t;
    const __half* Abase = Ag + (size_t)m0 * KDIM;
    const __half* Bbase = Bg + (size_t)n0 * KDIM;

    // cp.async stage loader: A 512 chunks of 16B, B 1024 chunks
    auto issue = [&](int st, int kt) {
        const uint32_t sA = smem_base + st * STAGE_BYTES;
        const uint32_t sB = sA + A_STAGE_BYTES;
        const int kofs = kt * TK;
        #pragma unroll
        for (int u = 0; u < 2; u++) {
            const int c = u * 256 + tid, r = c >> 2, ch = c & 3;
            CP_ASYNC16(sA + r * 80 + ch * 16,
                       Abase + (size_t)r * KDIM + kofs + ch * 8);
        }
        #pragma unroll
        for (int u = 0; u < 4; u++) {
            const int c = u * 256 + tid, r = c >> 2, ch = c & 3;
            CP_ASYNC16(sB + r * 80 + ch * 16,
                       Bbase + (size_t)r * KDIM + kofs + ch * 8);
        }
        CP_COMMIT();
    };

    float c[4][8][4];
    #pragma unroll
    for (int i = 0; i < 4; i++)
        #pragma unroll
        for (int j = 0; j < 8; j++)
            #pragma unroll
            for (int r = 0; r < 4; r++) c[i][j][r] = 0.0f;

    constexpr int T = KDIM / TK;
    issue(0, 0);
    issue(1, 1);

    // lane-dependent ldmatrix base offsets (within a stage)
    const uint32_t aOfs = (uint32_t)((wm + (lane & 15)) * 80 + (lane >> 4) * 16);
    const uint32_t bOfs = (uint32_t)((wn + (lane & 7)) * 80 + ((lane >> 3) & 1) * 16);

    #pragma unroll 1
    for (int it = 0; it < T; it++) {
        if (it < T - 1) asm volatile("cp.async.wait_group 1;" ::: "memory");
        else            asm volatile("cp.async.wait_group 0;" ::: "memory");
        __syncthreads();
        if (it + 2 < T) issue((it + 2) % 3, it + 2);

        const uint32_t sA = smem_base + (it % 3) * STAGE_BYTES;
        const uint32_t sB = sA + A_STAGE_BYTES;
        const uint32_t aAddr = sA + aOfs;
        const uint32_t bAddr = sB + bOfs;

        #pragma unroll
        for (int s2 = 0; s2 < 2; s2++) {
            uint32_t a[4][4], b[8][2];
            #pragma unroll
            for (int i = 0; i < 4; i++)
                ldm_x4(a[i], aAddr + i * (16 * 80) + s2 * 32);
            #pragma unroll
            for (int j = 0; j < 8; j++)
                ldm_x2(b[j], bAddr + j * (8 * 80) + s2 * 32);
            #pragma unroll
            for (int i = 0; i < 4; i++)
                #pragma unroll
                for (int j = 0; j < 8; j++)
                    mma_f16(c[i][j], a[i], b[j]);
        }
    }

    // ===== epilogue =====  (row m = m0+wm+16i+g (+8); b = m % 8 = g)
    if (MODE == 0) {
        const int e = n0 >> 9;   // TN=256 divides the 512-wide expert blocks
        const float gate = g_gates[g * E_NUM + e];
        float bj0[8], bj1[8];
        #pragma unroll
        for (int j = 0; j < 8; j++) {
            const int nc = n0 + wn + 8 * j + 2 * tq;
            bj0[j] = bias1[nc]; bj1[j] = bias1[nc + 1];
        }
        #pragma unroll
        for (int i = 0; i < 4; i++) {
            const int m = m0 + wm + 16 * i + g;
            __half* d0 = g_h + (size_t)m * N1;
            __half* d1 = g_h + (size_t)(m + 8) * N1;
            #pragma unroll
            for (int j = 0; j < 8; j++) {
                const int nc = n0 + wn + 8 * j + 2 * tq;
                *(__half2*)(d0 + nc) = __floats2half2_rn(
                    fmaxf(c[i][j][0] + bj0[j], 0.0f) * gate,
                    fmaxf(c[i][j][1] + bj1[j], 0.0f) * gate);
                *(__half2*)(d1 + nc) = __floats2half2_rn(
                    fmaxf(c[i][j][2] + bj0[j], 0.0f) * gate,
                    fmaxf(c[i][j][3] + bj1[j], 0.0f) * gate);
            }
        }
    } else {
        float2 bg[8];
        #pragma unroll
        for (int j = 0; j < 8; j++)
            bg[j] = *(const float2*)(g_b2g + g * D_DIM + n0 + wn + 8 * j + 2 * tq);
        #pragma unroll
        for (int i = 0; i < 4; i++) {
            const int m = m0 + wm + 16 * i + g;
            #pragma unroll
            for (int j = 0; j < 8; j++) {
                const int nc = n0 + wn + 8 * j + 2 * tq;
                const float2 r0 = *(const float2*)(xres + (size_t)m * D_DIM + nc);
                const float2 r1 = *(const float2*)(xres + (size_t)(m + 8) * D_DIM + nc);
                float2 o;
                o.x = c[i][j][0] + r0.x + bg[j].x;
                o.y = c[i][j][1] + r0.y + bg[j].y;
                *(float2*)(Cout + (size_t)m * D_DIM + nc) = o;
                o.x = c[i][j][2] + r1.x + bg[j].x;
                o.y = c[i][j][3] + r1.y + bg[j].y;
                *(float2*)(Cout + (size_t)(m + 8) * D_DIM + nc) = o;
            }
        }
    }
}

// ===================== launch =====================

extern "C" void kernel_launch(void* const* d_in, const int* in_sizes, int n_in,
                              void* d_out, int out_size) {
    if (n_in < 9) return;
    const float*         x   = (const float*)d_in[0];
    const unsigned char* pad = (const unsigned char*)d_in[1];
    const float*         gw  = (const float*)d_in[2];
    const float*         gam = (const float*)d_in[3];
    const float*         bet = (const float*)d_in[4];
    const float*         w1  = (const float*)d_in[5];
    const float*         b1  = (const float*)d_in[6];
    const float*         w2  = (const float*)d_in[7];
    const float*         b2  = (const float*)d_in[8];
    float* out = (float*)d_out;
    float* out_logits = out + (size_t)M_TOK * D_DIM;

    cudaFuncSetAttribute(k_mm<0, D_DIM>, cudaFuncAttributeMaxDynamicSharedMemorySize, GEMM_SMEM);
    cudaFuncSetAttribute(k_mm<1, N1>,    cudaFuncAttributeMaxDynamicSharedMemorySize, GEMM_SMEM);

    k_xn<<<M_TOK, 128>>>(x, gam, bet);
    k_maxpool<<<B_SZ * (D_DIM / 128), 128>>>(x, pad);
    k_gate<<<1, 256>>>(gw, b2, out_logits);
    k_w1t<<<dim3(H_DIM / 32, D_DIM / 32, E_NUM), dim3(32, 8)>>>(w1);
    k_w2t<<<dim3(N1 / 32, D_DIM / 32), dim3(32, 8)>>>(w2);

    k_mm<0, D_DIM><<<dim3(N1 / TN, M_TOK / TM), 256, GEMM_SMEM>>>(b1, nullptr, nullptr);
    k_mm<1, N1><<<dim3(D_DIM / TN, M_TOK / TM), 256, GEMM_SMEM>>>(nullptr, x, out);
}

// round 6
// speedup vs baseline: 2.5324x; 1.1378x over previous
#include <cuda_runtime.h>
#include <cuda_fp16.h>
#include <cstdint>
#include <math.h>

#define S_LEN 2048
#define B_SZ  8
#define D_DIM 1024
#define E_NUM 8
#define H_DIM 512
#define M_TOK (S_LEN * B_SZ)          // 16384
#define N1    (E_NUM * H_DIM)         // 4096

// ===================== scratch (__device__ globals: no allocs allowed) =====================
__device__ __half g_h  [(size_t)M_TOK * N1];     // fc1 activations (fp16)
__device__ __half g_xn [(size_t)M_TOK * D_DIM];  // LN(x) fp16
__device__ __half g_w1t[(size_t)N1 * D_DIM];     // W1^T per expert: [e*H+h][d]
__device__ __half g_w2t[(size_t)D_DIM * N1];     // W2^T: [d][e*H+h]
__device__ float  g_sx [B_SZ * D_DIM];
__device__ float  g_gates[B_SZ * E_NUM];
__device__ float  g_b2g[B_SZ * D_DIM];

// ===================== helpers =====================
__device__ __forceinline__ uint32_t smem_u32(const void* p) {
    uint32_t a;
    asm("{ .reg .u64 t; cvta.to.shared.u64 t, %1; cvt.u32.u64 %0, t; }" : "=r"(a) : "l"(p));
    return a;
}

#define CP_ASYNC16(dst, src) \
    asm volatile("cp.async.cg.shared.global [%0], [%1], 16;" :: "r"(dst), "l"(src))
#define CP_COMMIT() asm volatile("cp.async.commit_group;" ::: "memory")

__device__ __forceinline__ void ldm_x4(uint32_t r[4], uint32_t addr) {
    asm volatile("ldmatrix.sync.aligned.m8n8.x4.shared.b16 {%0,%1,%2,%3}, [%4];"
        : "=r"(r[0]), "=r"(r[1]), "=r"(r[2]), "=r"(r[3]) : "r"(addr));
}
__device__ __forceinline__ void mma_f16(float c[4], const uint32_t a[4], const uint32_t b[2]) {
    asm volatile(
        "mma.sync.aligned.m16n8k16.row.col.f32.f16.f16.f32 "
        "{%0,%1,%2,%3}, {%4,%5,%6,%7}, {%8,%9}, {%0,%1,%2,%3};"
        : "+f"(c[0]), "+f"(c[1]), "+f"(c[2]), "+f"(c[3])
        : "r"(a[0]), "r"(a[1]), "r"(a[2]), "r"(a[3]), "r"(b[0]), "r"(b[1]));
}

// ===================== prep kernels =====================

// fused LayerNorm -> g_xn (fp16)
__global__ void k_xn(const float* __restrict__ x,
                     const float* __restrict__ gamma, const float* __restrict__ beta) {
    const int m = blockIdx.x, t = threadIdx.x;  // 128 threads
    const float4* row = (const float4*)(x + (size_t)m * D_DIM);
    float4 v0 = row[t], v1 = row[t + 128];
    float s = v0.x + v0.y + v0.z + v0.w + v1.x + v1.y + v1.z + v1.w;
    float q = v0.x*v0.x + v0.y*v0.y + v0.z*v0.z + v0.w*v0.w
            + v1.x*v1.x + v1.y*v1.y + v1.z*v1.z + v1.w*v1.w;
    #pragma unroll
    for (int o = 16; o; o >>= 1) {
        s += __shfl_xor_sync(0xFFFFFFFFu, s, o);
        q += __shfl_xor_sync(0xFFFFFFFFu, q, o);
    }
    __shared__ float ss[4], sq[4], smu, srs;
    if ((t & 31) == 0) { ss[t >> 5] = s; sq[t >> 5] = q; }
    __syncthreads();
    if (t == 0) {
        float S2 = ss[0] + ss[1] + ss[2] + ss[3];
        float Q  = sq[0] + sq[1] + sq[2] + sq[3];
        float mu = S2 * (1.0f / D_DIM);
        smu = mu;
        srs = rsqrtf(Q * (1.0f / D_DIM) - mu * mu + 1e-5f);
    }
    __syncthreads();
    const float mu = smu, rs = srs;
    const float4* gam = (const float4*)gamma;
    const float4* bet = (const float4*)beta;
    __half2* out = (__half2*)(g_xn + (size_t)m * D_DIM);
    #pragma unroll
    for (int h = 0; h < 2; h++) {
        float4 v = (h == 0) ? v0 : v1;
        float4 ga = gam[t + h * 128], be = bet[t + h * 128];
        out[(t + h * 128) * 2 + 0] =
            __floats2half2_rn((v.x - mu) * rs * ga.x + be.x, (v.y - mu) * rs * ga.y + be.y);
        out[(t + h * 128) * 2 + 1] =
            __floats2half2_rn((v.z - mu) * rs * ga.z + be.z, (v.w - mu) * rs * ga.w + be.w);
    }
}

// masked max over sequence -> g_sx[b, d]
__global__ void k_maxpool(const float* __restrict__ x,
                          const unsigned char* __restrict__ pad) {
    const int b  = blockIdx.x >> 3;
    const int d0 = (blockIdx.x & 7) * 128;
    const int t  = threadIdx.x;  // 128
    __shared__ float neg[S_LEN];
    for (int s = t; s < S_LEN; s += 128)
        neg[s] = pad[b * S_LEN + s] ? -1e30f : 0.0f;
    __syncthreads();
    const int d = d0 + t;
    const float* base = x + (size_t)b * D_DIM + d;
    float m0 = -INFINITY, m1 = -INFINITY, m2 = -INFINITY, m3 = -INFINITY;
    #pragma unroll 1
    for (int s = 0; s < S_LEN; s += 4) {
        m0 = fmaxf(m0, base[(size_t)(s + 0) * (B_SZ * D_DIM)] + neg[s + 0]);
        m1 = fmaxf(m1, base[(size_t)(s + 1) * (B_SZ * D_DIM)] + neg[s + 1]);
        m2 = fmaxf(m2, base[(size_t)(s + 2) * (B_SZ * D_DIM)] + neg[s + 2]);
        m3 = fmaxf(m3, base[(size_t)(s + 3) * (B_SZ * D_DIM)] + neg[s + 3]);
    }
    g_sx[b * D_DIM + d] = fmaxf(fmaxf(m0, m1), fmaxf(m2, m3));
}

// gating: logits, softmax + renorm, gate-weighted b2
__global__ void k_gate(const float* __restrict__ gw,
                       const float* __restrict__ b2,
                       float* __restrict__ out_logits) {
    const int t = threadIdx.x;  // 256
    __shared__ float logits[B_SZ * E_NUM];
    __shared__ float gsh[B_SZ * E_NUM];
    if (t < B_SZ * E_NUM) {
        const int b = t >> 3, e = t & 7;
        const float4* sx = (const float4*)(g_sx + b * D_DIM);
        const float4* w  = (const float4*)(gw + e * D_DIM);
        float acc = 0.0f;
        for (int k = 0; k < D_DIM / 4; k++) {
            float4 a = sx[k]; float4 ww = w[k];
            acc += a.x * ww.x + a.y * ww.y + a.z * ww.z + a.w * ww.w;
        }
        logits[t] = acc;
        out_logits[b * E_NUM + e] = acc;
    }
    __syncthreads();
    if (t < B_SZ) {
        float mx = -INFINITY;
        for (int e = 0; e < E_NUM; e++) mx = fmaxf(mx, logits[t * E_NUM + e]);
        float p[E_NUM]; float ssum = 0.0f;
        for (int e = 0; e < E_NUM; e++) { p[e] = expf(logits[t * E_NUM + e] - mx); ssum += p[e]; }
        float s2 = 0.0f;
        for (int e = 0; e < E_NUM; e++) { p[e] /= ssum; s2 += p[e]; }
        for (int e = 0; e < E_NUM; e++) {
            float gv = p[e] / (s2 + 1e-9f);
            gsh[t * E_NUM + e] = gv;
            g_gates[t * E_NUM + e] = gv;
        }
    }
    __syncthreads();
    for (int i = t; i < B_SZ * D_DIM; i += 256) {
        const int b = i >> 10, d = i & 1023;
        float acc = 0.0f;
        #pragma unroll
        for (int e = 0; e < E_NUM; e++) acc += gsh[b * E_NUM + e] * b2[e * D_DIM + d];
        g_b2g[i] = acc;
    }
}

// W1 [E][D][H] -> g_w1t [(e*H+h)][d]  (fp16)
__global__ void k_w1t(const float* __restrict__ w1) {
    __shared__ float tbuf[32][33];
    const int h0 = blockIdx.x * 32, d0 = blockIdx.y * 32, e = blockIdx.z;
    const int tx = threadIdx.x, ty = threadIdx.y;  // (32, 8)
    const float* src = w1 + (size_t)e * D_DIM * H_DIM;
    #pragma unroll
    for (int i = 0; i < 32; i += 8)
        tbuf[ty + i][tx] = src[(size_t)(d0 + ty + i) * H_DIM + h0 + tx];
    __syncthreads();
    __half* dst = g_w1t + (size_t)(e * H_DIM + h0) * D_DIM + d0;
    #pragma unroll
    for (int i = 0; i < 32; i += 8)
        dst[(size_t)(ty + i) * D_DIM + tx] = __float2half_rn(tbuf[tx][ty + i]);
}

// W2 [E*H][D] -> g_w2t [d][E*H]  (fp16)
__global__ void k_w2t(const float* __restrict__ w2) {
    __shared__ float tbuf[32][33];
    const int k0 = blockIdx.x * 32, d0 = blockIdx.y * 32;
    const int tx = threadIdx.x, ty = threadIdx.y;
    #pragma unroll
    for (int i = 0; i < 32; i += 8)
        tbuf[ty + i][tx] = w2[(size_t)(k0 + ty + i) * D_DIM + d0 + tx];
    __syncthreads();
    __half* dst = g_w2t + (size_t)d0 * N1 + k0;
    #pragma unroll
    for (int i = 0; i < 32; i += 8)
        dst[(size_t)(ty + i) * N1 + tx] = __float2half_rn(tbuf[tx][ty + i]);
}

// ===================== fp16 mma.sync GEMM, TK=64, ldmatrix x4, cp.async 3-stage =====================
// MODE 0: fc1  g_h = fp16(relu(g_xn @ g_w1t^T + b1) * gate)   [M=16384, N=4096, K=1024]
// MODE 1: fc2  out = g_h @ g_w2t^T + x + b2g                  [M=16384, N=1024, K=4096]

#define TM 128
#define TN 256
#define TK 64
#define NSTAGE 3
#define ROW_H 72                                       // halfs: 64 + 8 pad = 144 B rows
#define ROW_B 144
#define A_STAGE_BYTES (TM * ROW_B)                     // 18432
#define B_STAGE_BYTES (TN * ROW_B)                     // 36864
#define STAGE_BYTES (A_STAGE_BYTES + B_STAGE_BYTES)    // 55296
#define GEMM_SMEM (NSTAGE * STAGE_BYTES + 256)         // ~166 KB

template<int MODE, int KDIM>
__global__ void __launch_bounds__(256, 1)
k_mm(const float* __restrict__ bias1, const float* __restrict__ xres,
     float* __restrict__ Cout)
{
    extern __shared__ __align__(128) char dsm[];
    const uint32_t smem_base = (smem_u32(dsm) + 127u) & ~127u;

    const int tid = threadIdx.x;
    const int wid = tid >> 5, lane = tid & 31;
    const int m0 = blockIdx.y * TM, n0 = blockIdx.x * TN;
    const int wm = (wid >> 2) * 64;      // 0 or 64
    const int wn = (wid & 3) * 64;       // 0,64,128,192
    const int g  = lane >> 2;            // 0..7
    const int tq = lane & 3;             // 0..3

    const __half* Ag = (MODE == 0) ? g_xn : g_h;
    const __half* Bg = (MODE == 0) ? g_w1t : g_w2t;
    const __half* Abase = Ag + (size_t)m0 * KDIM;
    const __half* Bbase = Bg + (size_t)n0 * KDIM;

    // cp.async loader: rows of 64 halfs = 8 chunks of 16B. A: 1024 chunks, B: 2048 chunks.
    auto issue = [&](int st, int kt) {
        const uint32_t sA = smem_base + st * STAGE_BYTES;
        const uint32_t sB = sA + A_STAGE_BYTES;
        const int kofs = kt * TK;
        #pragma unroll
        for (int u = 0; u < 4; u++) {
            const int c = u * 256 + tid, r = c >> 3, ch = c & 7;
            CP_ASYNC16(sA + r * ROW_B + ch * 16,
                       Abase + (size_t)r * KDIM + kofs + ch * 8);
        }
        #pragma unroll
        for (int u = 0; u < 8; u++) {
            const int c = u * 256 + tid, r = c >> 3, ch = c & 7;
            CP_ASYNC16(sB + r * ROW_B + ch * 16,
                       Bbase + (size_t)r * KDIM + kofs + ch * 8);
        }
        CP_COMMIT();
    };

    float c[4][8][4];
    #pragma unroll
    for (int i = 0; i < 4; i++)
        #pragma unroll
        for (int j = 0; j < 8; j++)
            #pragma unroll
            for (int r = 0; r < 4; r++) c[i][j][r] = 0.0f;

    constexpr int T = KDIM / TK;
    issue(0, 0);
    issue(1, 1);

    // lane-dependent ldmatrix base offsets (within a stage):
    // A x4: lanes 0-15 -> rows wm+(lane&15) k-low16B; lanes 16-31 same rows k+16B
    //   -> r0..r3 = a0(m0-7,klo), a1(m8-15,klo), a2(m0-7,khi), a3(m8-15,khi)  [mma a-frag order]
    const uint32_t aOfs = (uint32_t)((wm + (lane & 15)) * ROW_B + (lane >> 4) * 16);
    // B x4 (two n-tiles per ld): lanes 0-7 -> n-tile 2jj rows, klo; 8-15 -> same, khi;
    //   16-23 -> n-tile 2jj+1, klo; 24-31 -> khi.  r0,r1 = b[2jj]; r2,r3 = b[2jj+1]
    const uint32_t bOfs = (uint32_t)((((lane >> 4) & 1) * 8 + (lane & 7)) * ROW_B
                                     + ((lane >> 3) & 1) * 16);

    #pragma unroll 1
    for (int it = 0; it < T; it++) {
        if (it < T - 1) asm volatile("cp.async.wait_group 1;" ::: "memory");
        else            asm volatile("cp.async.wait_group 0;" ::: "memory");
        __syncthreads();
        if (it + 2 < T) issue((it + 2) % 3, it + 2);

        const uint32_t sA = smem_base + (it % 3) * STAGE_BYTES;
        const uint32_t sB = sA + A_STAGE_BYTES;
        const uint32_t aAddr = sA + aOfs;
        const uint32_t bAddr = sB + (wn * ROW_B) + bOfs;

        #pragma unroll
        for (int ks = 0; ks < 4; ks++) {          // 4 x k16 per 64-k stage
            uint32_t a[4][4], b[4][4];
            #pragma unroll
            for (int i = 0; i < 4; i++)
                ldm_x4(a[i], aAddr + i * (16 * ROW_B) + ks * 32);
            #pragma unroll
            for (int jj = 0; jj < 4; jj++)
                ldm_x4(b[jj], bAddr + jj * (16 * ROW_B) + ks * 32);
            #pragma unroll
            for (int i = 0; i < 4; i++)
                #pragma unroll
                for (int j = 0; j < 8; j++)
                    mma_f16(c[i][j], a[i], &b[j >> 1][(j & 1) * 2]);
        }
    }

    // ===== epilogue =====  (row m = m0+wm+16i+g (+8); b = m % 8 = g)
    if (MODE == 0) {
        const int e = n0 >> 9;   // TN=256 divides the 512-wide expert blocks
        const float gate = g_gates[g * E_NUM + e];
        float bj0[8], bj1[8];
        #pragma unroll
        for (int j = 0; j < 8; j++) {
            const int nc = n0 + wn + 8 * j + 2 * tq;
            bj0[j] = bias1[nc]; bj1[j] = bias1[nc + 1];
        }
        #pragma unroll
        for (int i = 0; i < 4; i++) {
            const int m = m0 + wm + 16 * i + g;
            __half* d0 = g_h + (size_t)m * N1;
            __half* d1 = g_h + (size_t)(m + 8) * N1;
            #pragma unroll
            for (int j = 0; j < 8; j++) {
                const int nc = n0 + wn + 8 * j + 2 * tq;
                *(__half2*)(d0 + nc) = __floats2half2_rn(
                    fmaxf(c[i][j][0] + bj0[j], 0.0f) * gate,
                    fmaxf(c[i][j][1] + bj1[j], 0.0f) * gate);
                *(__half2*)(d1 + nc) = __floats2half2_rn(
                    fmaxf(c[i][j][2] + bj0[j], 0.0f) * gate,
                    fmaxf(c[i][j][3] + bj1[j], 0.0f) * gate);
            }
        }
    } else {
        float2 bg[8];
        #pragma unroll
        for (int j = 0; j < 8; j++)
            bg[j] = *(const float2*)(g_b2g + g * D_DIM + n0 + wn + 8 * j + 2 * tq);
        #pragma unroll
        for (int i = 0; i < 4; i++) {
            const int m = m0 + wm + 16 * i + g;
            #pragma unroll
            for (int j = 0; j < 8; j++) {
                const int nc = n0 + wn + 8 * j + 2 * tq;
                const float2 r0 = *(const float2*)(xres + (size_t)m * D_DIM + nc);
                const float2 r1 = *(const float2*)(xres + (size_t)(m + 8) * D_DIM + nc);
                float2 o;
                o.x = c[i][j][0] + r0.x + bg[j].x;
                o.y = c[i][j][1] + r0.y + bg[j].y;
                *(float2*)(Cout + (size_t)m * D_DIM + nc) = o;
                o.x = c[i][j][2] + r1.x + bg[j].x;
                o.y = c[i][j][3] + r1.y + bg[j].y;
                *(float2*)(Cout + (size_t)(m + 8) * D_DIM + nc) = o;
            }
        }
    }
}

// ===================== launch =====================

extern "C" void kernel_launch(void* const* d_in, const int* in_sizes, int n_in,
                              void* d_out, int out_size) {
    if (n_in < 9) return;
    const float*         x   = (const float*)d_in[0];
    const unsigned char* pad = (const unsigned char*)d_in[1];
    const float*         gw  = (const float*)d_in[2];
    const float*         gam = (const float*)d_in[3];
    const float*         bet = (const float*)d_in[4];
    const float*         w1  = (const float*)d_in[5];
    const float*         b1  = (const float*)d_in[6];
    const float*         w2  = (const float*)d_in[7];
    const float*         b2  = (const float*)d_in[8];
    float* out = (float*)d_out;
    float* out_logits = out + (size_t)M_TOK * D_DIM;

    cudaFuncSetAttribute(k_mm<0, D_DIM>, cudaFuncAttributeMaxDynamicSharedMemorySize, GEMM_SMEM);
    cudaFuncSetAttribute(k_mm<1, N1>,    cudaFuncAttributeMaxDynamicSharedMemorySize, GEMM_SMEM);

    k_xn<<<M_TOK, 128>>>(x, gam, bet);
    k_maxpool<<<B_SZ * (D_DIM / 128), 128>>>(x, pad);
    k_gate<<<1, 256>>>(gw, b2, out_logits);
    k_w1t<<<dim3(H_DIM / 32, D_DIM / 32, E_NUM), dim3(32, 8)>>>(w1);
    k_w2t<<<dim3(N1 / 32, D_DIM / 32), dim3(32, 8)>>>(w2);

    k_mm<0, D_DIM><<<dim3(N1 / TN, M_TOK / TM), 256, GEMM_SMEM>>>(b1, nullptr, nullptr);
    k_mm<1, N1><<<dim3(D_DIM / TN, M_TOK / TM), 256, GEMM_SMEM>>>(nullptr, x, out);
}

// round 9
// speedup vs baseline: 2.5610x; 1.0113x over previous
#include <cuda_runtime.h>
#include <cuda_fp16.h>
#include <cstdint>
#include <math.h>

#define S_LEN 2048
#define B_SZ  8
#define D_DIM 1024
#define E_NUM 8
#define H_DIM 512
#define M_TOK (S_LEN * B_SZ)          // 16384
#define N1    (E_NUM * H_DIM)         // 4096

// ===================== scratch (__device__ globals: no allocs allowed) =====================
__device__ __half g_h  [(size_t)M_TOK * N1];     // fc1 activations (fp16)
__device__ __half g_xn [(size_t)M_TOK * D_DIM];  // LN(x) fp16
__device__ __half g_w1t[(size_t)N1 * D_DIM];     // W1^T per expert: [e*H+h][d]
__device__ __half g_w2t[(size_t)D_DIM * N1];     // W2^T: [d][e*H+h]
__device__ float  g_sx [B_SZ * D_DIM];
__device__ float  g_gates[B_SZ * E_NUM];
__device__ float  g_b2g[B_SZ * D_DIM];

// ===================== helpers =====================
__device__ __forceinline__ uint32_t smem_u32(const void* p) {
    uint32_t a;
    asm("{ .reg .u64 t; cvta.to.shared.u64 t, %1; cvt.u32.u64 %0, t; }" : "=r"(a) : "l"(p));
    return a;
}

#define CP_ASYNC16(dst, src) \
    asm volatile("cp.async.cg.shared.global [%0], [%1], 16;" :: "r"(dst), "l"(src))
#define CP_COMMIT() asm volatile("cp.async.commit_group;" ::: "memory")

__device__ __forceinline__ void ldm_x4(uint32_t r[4], uint32_t addr) {
    asm volatile("ldmatrix.sync.aligned.m8n8.x4.shared.b16 {%0,%1,%2,%3}, [%4];"
        : "=r"(r[0]), "=r"(r[1]), "=r"(r[2]), "=r"(r[3]) : "r"(addr));
}
__device__ __forceinline__ void mma_f16(float c[4], const uint32_t a[4], const uint32_t b[2]) {
    asm volatile(
        "mma.sync.aligned.m16n8k16.row.col.f32.f16.f16.f32 "
        "{%0,%1,%2,%3}, {%4,%5,%6,%7}, {%8,%9}, {%0,%1,%2,%3};"
        : "+f"(c[0]), "+f"(c[1]), "+f"(c[2]), "+f"(c[3])
        : "r"(a[0]), "r"(a[1]), "r"(a[2]), "r"(a[3]), "r"(b[0]), "r"(b[1]));
}

// ===================== prep kernels =====================

// fused LayerNorm -> g_xn (fp16)
__global__ void k_xn(const float* __restrict__ x,
                     const float* __restrict__ gamma, const float* __restrict__ beta) {
    const int m = blockIdx.x, t = threadIdx.x;  // 128 threads
    const float4* row = (const float4*)(x + (size_t)m * D_DIM);
    float4 v0 = row[t], v1 = row[t + 128];
    float s = v0.x + v0.y + v0.z + v0.w + v1.x + v1.y + v1.z + v1.w;
    float q = v0.x*v0.x + v0.y*v0.y + v0.z*v0.z + v0.w*v0.w
            + v1.x*v1.x + v1.y*v1.y + v1.z*v1.z + v1.w*v1.w;
    #pragma unroll
    for (int o = 16; o; o >>= 1) {
        s += __shfl_xor_sync(0xFFFFFFFFu, s, o);
        q += __shfl_xor_sync(0xFFFFFFFFu, q, o);
    }
    __shared__ float ss[4], sq[4], smu, srs;
    if ((t & 31) == 0) { ss[t >> 5] = s; sq[t >> 5] = q; }
    __syncthreads();
    if (t == 0) {
        float S2 = ss[0] + ss[1] + ss[2] + ss[3];
        float Q  = sq[0] + sq[1] + sq[2] + sq[3];
        float mu = S2 * (1.0f / D_DIM);
        smu = mu;
        srs = rsqrtf(Q * (1.0f / D_DIM) - mu * mu + 1e-5f);
    }
    __syncthreads();
    const float mu = smu, rs = srs;
    const float4* gam = (const float4*)gamma;
    const float4* bet = (const float4*)beta;
    __half2* out = (__half2*)(g_xn + (size_t)m * D_DIM);
    #pragma unroll
    for (int h = 0; h < 2; h++) {
        float4 v = (h == 0) ? v0 : v1;
        float4 ga = gam[t + h * 128], be = bet[t + h * 128];
        out[(t + h * 128) * 2 + 0] =
            __floats2half2_rn((v.x - mu) * rs * ga.x + be.x, (v.y - mu) * rs * ga.y + be.y);
        out[(t + h * 128) * 2 + 1] =
            __floats2half2_rn((v.z - mu) * rs * ga.z + be.z, (v.w - mu) * rs * ga.w + be.w);
    }
}

// masked max over sequence -> g_sx[b, d]
__global__ void k_maxpool(const float* __restrict__ x,
                          const unsigned char* __restrict__ pad) {
    const int b  = blockIdx.x >> 3;
    const int d0 = (blockIdx.x & 7) * 128;
    const int t  = threadIdx.x;  // 128
    __shared__ float neg[S_LEN];
    for (int s = t; s < S_LEN; s += 128)
        neg[s] = pad[b * S_LEN + s] ? -1e30f : 0.0f;
    __syncthreads();
    const int d = d0 + t;
    const float* base = x + (size_t)b * D_DIM + d;
    float m0 = -INFINITY, m1 = -INFINITY, m2 = -INFINITY, m3 = -INFINITY;
    #pragma unroll 1
    for (int s = 0; s < S_LEN; s += 4) {
        m0 = fmaxf(m0, base[(size_t)(s + 0) * (B_SZ * D_DIM)] + neg[s + 0]);
        m1 = fmaxf(m1, base[(size_t)(s + 1) * (B_SZ * D_DIM)] + neg[s + 1]);
        m2 = fmaxf(m2, base[(size_t)(s + 2) * (B_SZ * D_DIM)] + neg[s + 2]);
        m3 = fmaxf(m3, base[(size_t)(s + 3) * (B_SZ * D_DIM)] + neg[s + 3]);
    }
    g_sx[b * D_DIM + d] = fmaxf(fmaxf(m0, m1), fmaxf(m2, m3));
}

// gating: logits, softmax + renorm, gate-weighted b2
__global__ void k_gate(const float* __restrict__ gw,
                       const float* __restrict__ b2,
                       float* __restrict__ out_logits) {
    const int t = threadIdx.x;  // 256
    __shared__ float logits[B_SZ * E_NUM];
    __shared__ float gsh[B_SZ * E_NUM];
    if (t < B_SZ * E_NUM) {
        const int b = t >> 3, e = t & 7;
        const float4* sx = (const float4*)(g_sx + b * D_DIM);
        const float4* w  = (const float4*)(gw + e * D_DIM);
        float acc = 0.0f;
        for (int k = 0; k < D_DIM / 4; k++) {
            float4 a = sx[k]; float4 ww = w[k];
            acc += a.x * ww.x + a.y * ww.y + a.z * ww.z + a.w * ww.w;
        }
        logits[t] = acc;
        out_logits[b * E_NUM + e] = acc;
    }
    __syncthreads();
    if (t < B_SZ) {
        float mx = -INFINITY;
        for (int e = 0; e < E_NUM; e++) mx = fmaxf(mx, logits[t * E_NUM + e]);
        float p[E_NUM]; float ssum = 0.0f;
        for (int e = 0; e < E_NUM; e++) { p[e] = expf(logits[t * E_NUM + e] - mx); ssum += p[e]; }
        float s2 = 0.0f;
        for (int e = 0; e < E_NUM; e++) { p[e] /= ssum; s2 += p[e]; }
        for (int e = 0; e < E_NUM; e++) {
            float gv = p[e] / (s2 + 1e-9f);
            gsh[t * E_NUM + e] = gv;
            g_gates[t * E_NUM + e] = gv;
        }
    }
    __syncthreads();
    for (int i = t; i < B_SZ * D_DIM; i += 256) {
        const int b = i >> 10, d = i & 1023;
        float acc = 0.0f;
        #pragma unroll
        for (int e = 0; e < E_NUM; e++) acc += gsh[b * E_NUM + e] * b2[e * D_DIM + d];
        g_b2g[i] = acc;
    }
}

// W1 [E][D][H] -> g_w1t [(e*H+h)][d]  (fp16)
__global__ void k_w1t(const float* __restrict__ w1) {
    __shared__ float tbuf[32][33];
    const int h0 = blockIdx.x * 32, d0 = blockIdx.y * 32, e = blockIdx.z;
    const int tx = threadIdx.x, ty = threadIdx.y;  // (32, 8)
    const float* src = w1 + (size_t)e * D_DIM * H_DIM;
    #pragma unroll
    for (int i = 0; i < 32; i += 8)
        tbuf[ty + i][tx] = src[(size_t)(d0 + ty + i) * H_DIM + h0 + tx];
    __syncthreads();
    __half* dst = g_w1t + (size_t)(e * H_DIM + h0) * D_DIM + d0;
    #pragma unroll
    for (int i = 0; i < 32; i += 8)
        dst[(size_t)(ty + i) * D_DIM + tx] = __float2half_rn(tbuf[tx][ty + i]);
}

// W2 [E*H][D] -> g_w2t [d][E*H]  (fp16)
__global__ void k_w2t(const float* __restrict__ w2) {
    __shared__ float tbuf[32][33];
    const int k0 = blockIdx.x * 32, d0 = blockIdx.y * 32;
    const int tx = threadIdx.x, ty = threadIdx.y;
    #pragma unroll
    for (int i = 0; i < 32; i += 8)
        tbuf[ty + i][tx] = w2[(size_t)(k0 + ty + i) * D_DIM + d0 + tx];
    __syncthreads();
    __half* dst = g_w2t + (size_t)d0 * N1 + k0;
    #pragma unroll
    for (int i = 0; i < 32; i += 8)
        dst[(size_t)(ty + i) * N1 + tx] = __float2half_rn(tbuf[tx][ty + i]);
}

// ===================== fp16 mma.sync GEMM, 512 threads, TK=64, 3-stage =====================
// MODE 0: fc1  g_h = fp16(relu(g_xn @ g_w1t^T + b1) * gate)   [M=16384, N=4096, K=1024]
// MODE 1: fc2  out = g_h @ g_w2t^T + x + b2g                  [M=16384, N=1024, K=4096]

#define TM 128
#define TN 256
#define TK 64
#define NSTAGE 3
#define NTHR 512
#define ROW_B 144                                      // bytes: 64 halfs + 8 pad
#define A_STAGE_BYTES (TM * ROW_B)                     // 18432
#define B_STAGE_BYTES (TN * ROW_B)                     // 36864
#define STAGE_BYTES (A_STAGE_BYTES + B_STAGE_BYTES)    // 55296
#define GEMM_SMEM (NSTAGE * STAGE_BYTES + 256)         // ~166 KB

template<int MODE, int KDIM>
__global__ void __launch_bounds__(NTHR, 1)
k_mm(const float* __restrict__ bias1, const float* __restrict__ xres,
     float* __restrict__ Cout)
{
    extern __shared__ __align__(128) char dsm[];
    const uint32_t smem_base = (smem_u32(dsm) + 127u) & ~127u;

    const int tid = threadIdx.x;
    const int wid = tid >> 5, lane = tid & 31;
    const int m0 = blockIdx.y * TM, n0 = blockIdx.x * TN;
    const int wm = (wid >> 3) * 64;      // 0 or 64
    const int wn = (wid & 7) * 32;       // 0..224
    const int g  = lane >> 2;            // 0..7
    const int tq = lane & 3;             // 0..3

    const __half* Ag = (MODE == 0) ? g_xn : g_h;
    const __half* Bg = (MODE == 0) ? g_w1t : g_w2t;
    const __half* Abase = Ag + (size_t)m0 * KDIM;
    const __half* Bbase = Bg + (size_t)n0 * KDIM;

    // cp.async loader: rows of 64 halfs = 8 chunks of 16B. A: 1024 chunks, B: 2048 chunks.
    auto issue = [&](int st, int kt) {
        const uint32_t sA = smem_base + st * STAGE_BYTES;
        const uint32_t sB = sA + A_STAGE_BYTES;
        const int kofs = kt * TK;
        #pragma unroll
        for (int u = 0; u < 2; u++) {
            const int c = u * NTHR + tid, r = c >> 3, ch = c & 7;
            CP_ASYNC16(sA + r * ROW_B + ch * 16,
                       Abase + (size_t)r * KDIM + kofs + ch * 8);
        }
        #pragma unroll
        for (int u = 0; u < 4; u++) {
            const int c = u * NTHR + tid, r = c >> 3, ch = c & 7;
            CP_ASYNC16(sB + r * ROW_B + ch * 16,
                       Bbase + (size_t)r * KDIM + kofs + ch * 8);
        }
        CP_COMMIT();
    };

    float c[4][4][4];
    #pragma unroll
    for (int i = 0; i < 4; i++)
        #pragma unroll
        for (int j = 0; j < 4; j++)
            #pragma unroll
            for (int r = 0; r < 4; r++) c[i][j][r] = 0.0f;

    constexpr int T = KDIM / TK;
    issue(0, 0);
    issue(1, 1);

    // A x4: lanes 0-15 -> rows wm+(lane&15), k-low 16B; lanes 16-31 -> same rows, k+16B
    const uint32_t aOfs = (uint32_t)((wm + (lane & 15)) * ROW_B + (lane >> 4) * 16);
    // B x4 (two n8 tiles per ld): lanes 0-7 rows+0 klo, 8-15 rows+0 khi, 16-23 rows+8 klo, 24-31 rows+8 khi
    const uint32_t bOfs = (uint32_t)((wn + ((lane >> 4) & 1) * 8 + (lane & 7)) * ROW_B
                                     + ((lane >> 3) & 1) * 16);

    #pragma unroll 1
    for (int it = 0; it < T; it++) {
        if (it < T - 1) asm volatile("cp.async.wait_group 1;" ::: "memory");
        else            asm volatile("cp.async.wait_group 0;" ::: "memory");
        __syncthreads();
        if (it + 2 < T) issue((it + 2) % 3, it + 2);

        const uint32_t sA = smem_base + (it % 3) * STAGE_BYTES;
        const uint32_t sB = sA + A_STAGE_BYTES;
        const uint32_t aAddr = sA + aOfs;
        const uint32_t bAddr = sB + bOfs;

        #pragma unroll
        for (int ks = 0; ks < 4; ks++) {          // 4 x k16 per 64-k stage
            uint32_t a[4][4], b[2][4];
            #pragma unroll
            for (int i = 0; i < 4; i++)
                ldm_x4(a[i], aAddr + i * (16 * ROW_B) + ks * 32);
            #pragma unroll
            for (int jj = 0; jj < 2; jj++)
                ldm_x4(b[jj], bAddr + jj * (16 * ROW_B) + ks * 32);
            #pragma unroll
            for (int i = 0; i < 4; i++)
                #pragma unroll
                for (int j = 0; j < 4; j++)
                    mma_f16(c[i][j], a[i], &b[j >> 1][(j & 1) * 2]);
        }
    }

    // ===== epilogue =====  (row m = m0+wm+16i+g (+8); b = m % 8 = g)
    if (MODE == 0) {
        const int e = n0 >> 9;   // TN=256 divides the 512-wide expert blocks
        const float gate = g_gates[g * E_NUM + e];
        float bj0[4], bj1[4];
        #pragma unroll
        for (int j = 0; j < 4; j++) {
            const int nc = n0 + wn + 8 * j + 2 * tq;
            bj0[j] = bias1[nc]; bj1[j] = bias1[nc + 1];
        }
        #pragma unroll
        for (int i = 0; i < 4; i++) {
            const int m = m0 + wm + 16 * i + g;
            __half* d0 = g_h + (size_t)m * N1;
            __half* d1 = g_h + (size_t)(m + 8) * N1;
            #pragma unroll
            for (int j = 0; j < 4; j++) {
                const int nc = n0 + wn + 8 * j + 2 * tq;
                *(__half2*)(d0 + nc) = __floats2half2_rn(
                    fmaxf(c[i][j][0] + bj0[j], 0.0f) * gate,
                    fmaxf(c[i][j][1] + bj1[j], 0.0f) * gate);
                *(__half2*)(d1 + nc) = __floats2half2_rn(
                    fmaxf(c[i][j][2] + bj0[j], 0.0f) * gate,
                    fmaxf(c[i][j][3] + bj1[j], 0.0f) * gate);
            }
        }
    } else {
        float2 bg[4];
        #pragma unroll
        for (int j = 0; j < 4; j++)
            bg[j] = *(const float2*)(g_b2g + g * D_DIM + n0 + wn + 8 * j + 2 * tq);
        #pragma unroll
        for (int i = 0; i < 4; i++) {
            const int m = m0 + wm + 16 * i + g;
            #pragma unroll
            for (int j = 0; j < 4; j++) {
                const int nc = n0 + wn + 8 * j + 2 * tq;
                const float2 r0 = *(const float2*)(xres + (size_t)m * D_DIM + nc);
                const float2 r1 = *(const float2*)(xres + (size_t)(m + 8) * D_DIM + nc);
                float2 o;
                o.x = c[i][j][0] + r0.x + bg[j].x;
                o.y = c[i][j][1] + r0.y + bg[j].y;
                *(float2*)(Cout + (size_t)m * D_DIM + nc) = o;
                o.x = c[i][j][2] + r1.x + bg[j].x;
                o.y = c[i][j][3] + r1.y + bg[j].y;
                *(float2*)(Cout + (size_t)(m + 8) * D_DIM + nc) = o;
            }
        }
    }
}

// ===================== launch =====================

extern "C" void kernel_launch(void* const* d_in, const int* in_sizes, int n_in,
                              void* d_out, int out_size) {
    if (n_in < 9) return;
    const float*         x   = (const float*)d_in[0];
    const unsigned char* pad = (const unsigned char*)d_in[1];
    const float*         gw  = (const float*)d_in[2];
    const float*         gam = (const float*)d_in[3];
    const float*         bet = (const float*)d_in[4];
    const float*         w1  = (const float*)d_in[5];
    const float*         b1  = (const float*)d_in[6];
    const float*         w2  = (const float*)d_in[7];
    const float*         b2  = (const float*)d_in[8];
    float* out = (float*)d_out;
    float* out_logits = out + (size_t)M_TOK * D_DIM;

    cudaFuncSetAttribute(k_mm<0, D_DIM>, cudaFuncAttributeMaxDynamicSharedMemorySize, GEMM_SMEM);
    cudaFuncSetAttribute(k_mm<1, N1>,    cudaFuncAttributeMaxDynamicSharedMemorySize, GEMM_SMEM);

    k_xn<<<M_TOK, 128>>>(x, gam, bet);
    k_maxpool<<<B_SZ * (D_DIM / 128), 128>>>(x, pad);
    k_gate<<<1, 256>>>(gw, b2, out_logits);
    k_w1t<<<dim3(H_DIM / 32, D_DIM / 32, E_NUM), dim3(32, 8)>>>(w1);
    k_w2t<<<dim3(N1 / 32, D_DIM / 32), dim3(32, 8)>>>(w2);

    k_mm<0, D_DIM><<<dim3(N1 / TN, M_TOK / TM), NTHR, GEMM_SMEM>>>(b1, nullptr, nullptr);
    k_mm<1, N1><<<dim3(D_DIM / TN, M_TOK / TM), NTHR, GEMM_SMEM>>>(nullptr, x, out);
}